// round 16
// baseline (speedup 1.0000x reference)
#include <cuda_runtime.h>
#include <cstdint>

#define NN          8192
#define THREADS     1024
#define NWARPS      32
#define STAGES      6
#define STAGE_BYTES (NN * 4)            // 32 KiB per staged row
#define SMEM_DYN    (STAGES * STAGE_BYTES)
#define GRID        148

__device__ float g_zero = 0.0f;

// ---------------------------------------------------------------------------
// mbarrier / bulk-copy helpers
// ---------------------------------------------------------------------------
__device__ __forceinline__ void mbar_init(uint32_t addr, uint32_t cnt)
{
    asm volatile("mbarrier.init.shared.b64 [%0], %1;"
                 :: "r"(addr), "r"(cnt) : "memory");
}
__device__ __forceinline__ void mbar_arrive_expect_tx(uint32_t addr, uint32_t bytes)
{
    asm volatile("mbarrier.arrive.expect_tx.shared.b64 _, [%0], %1;"
                 :: "r"(addr), "r"(bytes) : "memory");
}
__device__ __forceinline__ void bulk_g2s(uint32_t dst, const void* src,
                                         uint32_t bytes, uint32_t mbar)
{
    asm volatile(
        "cp.async.bulk.shared::cta.global.mbarrier::complete_tx::bytes "
        "[%0], [%1], %2, [%3];"
        :: "r"(dst), "l"(src), "r"(bytes), "r"(mbar) : "memory");
}
__device__ __forceinline__ void mbar_wait(uint32_t addr, uint32_t parity)
{
    uint32_t done;
    asm volatile(
        "{\n\t.reg .pred p;\n\t"
        "mbarrier.try_wait.parity.acquire.cta.shared::cta.b64 p, [%1], %2;\n\t"
        "selp.b32 %0, 1, 0, p;\n\t}"
        : "=r"(done) : "r"(addr), "r"(parity) : "memory");
    if (!done) {
        asm volatile(
            "{\n\t.reg .pred P1;\n\t"
            "W_%=:\n\t"
            "mbarrier.try_wait.parity.acquire.cta.shared::cta.b64 P1, [%0], %1, 0x989680;\n\t"
            "@P1 bra.uni DONE_%=;\n\t"
            "bra.uni W_%=;\n\t"
            "DONE_%=:\n\t}"
            :: "r"(addr), "r"(parity) : "memory");
    }
}

// ---------------------------------------------------------------------------
// Block scan over two 4096-element sub-blocks. Thread t's 4-element groups
// sit at elements {4t..4t+3} (sub-block 0) and {4096+4t..} (sub-block 1).
// Input: inclusive sums t0, t1 of the thread's two groups. Output: exclusive
// global bases for each group. One __syncthreads inside. ws = 64-float buf.
// ---------------------------------------------------------------------------
__device__ __forceinline__ void block_scan2(float t0, float t1, float* ws,
                                            int lane, int wid,
                                            float& base0, float& base1)
{
    float sA = t0, sB = t1;
    #pragma unroll
    for (int o = 1; o < 32; o <<= 1) {
        float yA = __shfl_up_sync(0xFFFFFFFFu, sA, o);
        float yB = __shfl_up_sync(0xFFFFFFFFu, sB, o);
        if (lane >= o) { sA += yA; sB += yB; }
    }
    if (lane == 31) {
        ws[wid]      = sA;               // flat index wid       (sub-block 0)
        ws[32 + wid] = sB;               // flat index 32 + wid  (sub-block 1)
    }
    __syncthreads();

    // redundant 64-value exclusive scan in every warp: lane l owns flat 2l, 2l+1
    float u0 = ws[2 * lane];
    float u1 = ws[2 * lane + 1];
    float pr = u0 + u1;
    float S  = pr;
    #pragma unroll
    for (int o = 1; o < 32; o <<= 1) {
        float y = __shfl_up_sync(0xFFFFFFFFu, S, o);
        if (lane >= o) S += y;
    }
    float exlo = S - pr;                 // exclusive at flat 2l
    float exhi = S - u1;                 // exclusive at flat 2l+1

    // fetch exclusive prefixes at flat indices wid and 32+wid (uniform/warp)
    int i0 = wid, i1 = 32 + wid;
    float lo0 = __shfl_sync(0xFFFFFFFFu, exlo, i0 >> 1);
    float hi0 = __shfl_sync(0xFFFFFFFFu, exhi, i0 >> 1);
    float lo1 = __shfl_sync(0xFFFFFFFFu, exlo, i1 >> 1);
    float hi1 = __shfl_sync(0xFFFFFFFFu, exhi, i1 >> 1);
    float E0 = (i0 & 1) ? hi0 : lo0;
    float E1 = (i1 & 1) ? hi1 : lo1;

    base0 = E0 + (sA - t0);              // + lane-exclusive within warp
    base1 = E1 + (sB - t1);
}

// ---------------------------------------------------------------------------
// Persistent kernel: cp.async.bulk 6-stage smem ring feeds a one-pass block
// scan per row. DMA engine keeps HBM busy while warps compute.
// ---------------------------------------------------------------------------
__global__ void __launch_bounds__(THREADS, 1)
row_w1_kernel(const float* __restrict__ x, const float* __restrict__ bary,
              float* __restrict__ out, int D)
{
    extern __shared__ float ring[];                  // STAGES * NN floats
    __shared__ __align__(8) uint64_t mbar[STAGES];
    __shared__ float wsbuf[2][64];
    __shared__ float red[NWARPS];

    const int t    = threadIdx.x;
    const int lane = t & 31;
    const int wid  = t >> 5;
    const int b    = blockIdx.x;

    const uint32_t ring_base = (uint32_t)__cvta_generic_to_shared(ring);
    const uint32_t mbar_base = (uint32_t)__cvta_generic_to_shared(mbar);

    if (t == 0) {
        #pragma unroll
        for (int s = 0; s < STAGES; ++s)
            mbar_init(mbar_base + 8 * s, 1);
    }
    __syncthreads();

    // ---- prologue: issue bulk copies for the first STAGES rows ----
    if (t == 0) {
        #pragma unroll
        for (int k = 0; k < STAGES; ++k) {
            int r = b + GRID * k;
            if (r < D) {
                mbar_arrive_expect_tx(mbar_base + 8 * k, STAGE_BYTES);
                bulk_g2s(ring_base + k * STAGE_BYTES,
                         x + (size_t)r * NN, STAGE_BYTES, mbar_base + 8 * k);
            }
        }
    }

    // ---- cb = cumsum(bary) into registers (overlaps the TMA prologue) ----
    float4 cb0, cb1;
    {
        const float4* bp = reinterpret_cast<const float4*>(bary);
        float4 q0 = bp[t], q1 = bp[t + 1024];
        float a0 = q0.x, a1 = a0 + q0.y, a2 = a1 + q0.z, a3 = a2 + q0.w;
        float k0 = q1.x, k1 = k0 + q1.y, k2 = k1 + q1.z, k3 = k2 + q1.w;
        float b0, b1;
        block_scan2(a3, k3, &wsbuf[0][0], lane, wid, b0, b1);
        cb0.x = b0 + a0;  cb0.y = b0 + a1;  cb0.z = b0 + a2;  cb0.w = b0 + a3;
        cb1.x = b1 + k0;  cb1.y = b1 + k1;  cb1.z = b1 + k2;  cb1.w = b1 + k3;

        if (b == 0) {                    // bary -> out[1..N]
            float* o = out + 1 + 4 * t;
            o[0] = q0.x; o[1] = q0.y; o[2] = q0.z; o[3] = q0.w;
            o[4096 + 0] = q1.x; o[4096 + 1] = q1.y;
            o[4096 + 2] = q1.z; o[4096 + 3] = q1.w;
        }
    }
    __syncthreads();                     // wsbuf[0] reused by row 0

    // ---- main loop: one row per iteration ----
    float total = 0.0f;
    int i = 0;
    int row = b;
    while (row < D) {
        const int s = i % STAGES;
        const uint32_t par = (uint32_t)((i / STAGES) & 1);
        mbar_wait(mbar_base + 8 * s, par);

        const float4* rp = reinterpret_cast<const float4*>(ring + s * NN);
        float4 v0 = rp[t], v1 = rp[t + 1024];

        float a0 = v0.x, a1 = a0 + v0.y, a2 = a1 + v0.z, a3 = a2 + v0.w;
        float k0 = v1.x, k1 = k0 + v1.y, k2 = k1 + v1.z, k3 = k2 + v1.w;

        float b0, b1;
        block_scan2(a3, k3, &wsbuf[i & 1][0], lane, wid, b0, b1);

        float acc;
        acc  = fabsf(b0 + a0 - cb0.x);
        acc += fabsf(b0 + a1 - cb0.y);
        acc += fabsf(b0 + a2 - cb0.z);
        acc += fabsf(b0 + a3 - cb0.w);
        acc += fabsf(b1 + k0 - cb1.x);
        acc += fabsf(b1 + k1 - cb1.y);
        acc += fabsf(b1 + k2 - cb1.z);
        if (t != THREADS - 1)            // exclude global element N-1
            acc += fabsf(b1 + k3 - cb1.w);
        total += acc;

        __syncthreads();                 // stage s + wsbuf parity fully read

        if (t == 0) {
            int r2 = row + GRID * STAGES;
            if (r2 < D) {
                mbar_arrive_expect_tx(mbar_base + 8 * s, STAGE_BYTES);
                bulk_g2s(ring_base + s * STAGE_BYTES,
                         x + (size_t)r2 * NN, STAGE_BYTES, mbar_base + 8 * s);
            }
        }
        ++i; row += GRID;
    }

    // ---- block reduction + one atomic per block ----
    #pragma unroll
    for (int o = 16; o > 0; o >>= 1)
        total += __shfl_down_sync(0xFFFFFFFFu, total, o);
    if (lane == 0) red[wid] = total;
    __syncthreads();
    if (wid == 0) {
        float v = (lane < NWARPS) ? red[lane] : 0.0f;
        #pragma unroll
        for (int o = NWARPS / 2; o > 0; o >>= 1)
            v += __shfl_down_sync(0xFFFFFFFFu, v, o);
        if (lane == 0) atomicAdd(out, v);
    }
}

// ---------------------------------------------------------------------------
extern "C" void kernel_launch(void* const* d_in, const int* in_sizes, int n_in,
                              void* d_out, int out_size)
{
    const float* x    = (const float*)d_in[0];   // [D, N] f32
    const float* bary = (const float*)d_in[1];   // [N] f32
    float* out = (float*)d_out;

    const int N = in_sizes[1];
    const int D = in_sizes[0] / N;
    (void)n_in; (void)out_size; (void)N;

    // out[0] = 0 via tiny D2D copy (stream-ordered before the kernel's atomics)
    void* zp = nullptr;
    cudaGetSymbolAddress(&zp, g_zero);
    cudaMemcpyAsync(out, zp, sizeof(float), cudaMemcpyDeviceToDevice, 0);

    cudaFuncSetAttribute(row_w1_kernel,
                         cudaFuncAttributeMaxDynamicSharedMemorySize, SMEM_DYN);

    row_w1_kernel<<<GRID, THREADS, SMEM_DYN>>>(x, bary, out, D);
}